// round 1
// baseline (speedup 1.0000x reference)
#include <cuda_runtime.h>
#include <math.h>

#define N_NODES 50000
#define N_EDGES 800000
#define FEA     128      // HEADS*HID
#define HEADS   8
#define NCLS    10
#define NEG     0.2f

// ---------------- scratch (device globals: no allocation allowed) ------------
__device__ float g_feat[N_NODES * FEA];
__device__ float g_hA[N_NODES * FEA];
__device__ float g_hB[N_NODES * FEA];
__device__ float g_el[N_NODES * HEADS];
__device__ float g_er[N_NODES * HEADS];
__device__ float g_feat5[N_NODES * NCLS];
__device__ float g_el5[N_NODES];
__device__ float g_er5[N_NODES];
__device__ int   g_cnt[N_NODES];
__device__ int   g_cur[N_NODES];
__device__ int   g_off[N_NODES + 1];
__device__ int   g_ssrc[N_EDGES];

// ---------------- CSR build --------------------------------------------------
__global__ void zero_kernel() {
    int i = blockIdx.x * blockDim.x + threadIdx.x;
    if (i < N_NODES) { g_cnt[i] = 0; g_cur[i] = 0; }
}

__global__ void count_kernel(const int* __restrict__ dst) {
    int i = blockIdx.x * blockDim.x + threadIdx.x;
    if (i < N_EDGES) atomicAdd(&g_cnt[dst[i]], 1);
}

__global__ void scan_kernel() {   // single block, 1024 threads
    __shared__ int wsum[32];
    int tid = threadIdx.x, lane = tid & 31, wid = tid >> 5;
    int carry = 0;
    for (int base = 0; base < N_NODES; base += 1024) {
        int i = base + tid;
        int v = (i < N_NODES) ? g_cnt[i] : 0;
        int x = v;
        #pragma unroll
        for (int d = 1; d < 32; d <<= 1) {
            int t = __shfl_up_sync(0xffffffffu, x, d);
            if (lane >= d) x += t;
        }
        if (lane == 31) wsum[wid] = x;
        __syncthreads();
        if (wid == 0) {
            int s = wsum[lane];
            #pragma unroll
            for (int d = 1; d < 32; d <<= 1) {
                int t = __shfl_up_sync(0xffffffffu, s, d);
                if (lane >= d) s += t;
            }
            wsum[lane] = s;
        }
        __syncthreads();
        int pre = (wid > 0) ? wsum[wid - 1] : 0;
        int incl = x + pre;
        if (i < N_NODES) g_off[i] = carry + incl - v;   // exclusive
        carry += wsum[31];
        __syncthreads();
    }
    if (tid == 0) g_off[N_NODES] = carry;
}

__global__ void scatter_kernel(const int* __restrict__ src, const int* __restrict__ dst) {
    int i = blockIdx.x * blockDim.x + threadIdx.x;
    if (i < N_EDGES) {
        int d = dst[i];
        int p = atomicAdd(&g_cur[d], 1);
        g_ssrc[g_off[d] + p] = src[i];
    }
}

// ---------------- GEMM: (N,128) @ (128,128), fp32 ----------------------------
// 64 rows x 128 cols per block, 256 threads, 8x4 micro-tile per thread.
__global__ void gemm128_kernel(const float* __restrict__ hin,
                               const float* __restrict__ W,
                               float* __restrict__ out) {
    extern __shared__ float sm[];
    float* Ws = sm;            // 128*128
    float* hs = sm + 128 * 128; // 64*128
    int tid = threadIdx.x;
    int row0 = blockIdx.x * 64;

    const float4* W4p = (const float4*)W;
    float4* Ws4 = (float4*)Ws;
    #pragma unroll
    for (int i = 0; i < 16; i++) Ws4[tid + i * 256] = W4p[tid + i * 256];

    const float4* h4p = (const float4*)hin;
    float4* hs4 = (float4*)hs;
    #pragma unroll
    for (int i = 0; i < 8; i++) {
        int f4 = tid + i * 256;          // 0..2047
        int r = f4 >> 5, c = f4 & 31;
        int gr = row0 + r;
        float4 v = make_float4(0.f, 0.f, 0.f, 0.f);
        if (gr < N_NODES) v = h4p[gr * 32 + c];
        hs4[f4] = v;
    }
    __syncthreads();

    int ty = tid >> 5;   // warp id: rows [ty*8, ty*8+8)
    int tx = tid & 31;   // cols [tx*4, tx*4+4)
    float acc[8][4];
    #pragma unroll
    for (int r = 0; r < 8; r++)
        #pragma unroll
        for (int c = 0; c < 4; c++) acc[r][c] = 0.f;

    for (int k0 = 0; k0 < 128; k0 += 4) {
        float4 a[8];
        #pragma unroll
        for (int r = 0; r < 8; r++)
            a[r] = *(const float4*)&hs[(ty * 8 + r) * 128 + k0];
        #pragma unroll
        for (int kk = 0; kk < 4; kk++) {
            float4 b = *(const float4*)&Ws[(k0 + kk) * 128 + tx * 4];
            #pragma unroll
            for (int r = 0; r < 8; r++) {
                float av = (kk == 0) ? a[r].x : (kk == 1) ? a[r].y : (kk == 2) ? a[r].z : a[r].w;
                acc[r][0] += av * b.x;
                acc[r][1] += av * b.y;
                acc[r][2] += av * b.z;
                acc[r][3] += av * b.w;
            }
        }
    }
    #pragma unroll
    for (int r = 0; r < 8; r++) {
        int gr = row0 + ty * 8 + r;
        if (gr < N_NODES)
            *(float4*)&out[gr * 128 + tx * 4] =
                make_float4(acc[r][0], acc[r][1], acc[r][2], acc[r][3]);
    }
}

// ---------------- el/er per node ---------------------------------------------
__global__ void elr_kernel(const float* __restrict__ feat,
                           const float* __restrict__ al,
                           const float* __restrict__ ar) {
    int node = (blockIdx.x * blockDim.x + threadIdx.x) >> 5;
    int lane = threadIdx.x & 31;
    if (node >= N_NODES) return;
    float4 f = ((const float4*)feat)[node * 32 + lane];
    float4 a = ((const float4*)al)[lane];
    float4 b = ((const float4*)ar)[lane];
    float pl = f.x * a.x + f.y * a.y + f.z * a.z + f.w * a.w;
    float pr = f.x * b.x + f.y * b.y + f.z * b.z + f.w * b.w;
    pl += __shfl_xor_sync(0xffffffffu, pl, 1);
    pr += __shfl_xor_sync(0xffffffffu, pr, 1);
    pl += __shfl_xor_sync(0xffffffffu, pl, 2);
    pr += __shfl_xor_sync(0xffffffffu, pr, 2);
    if ((lane & 3) == 0) {
        g_el[node * 8 + (lane >> 2)] = pl;
        g_er[node * 8 + (lane >> 2)] = pr;
    }
}

__device__ __forceinline__ float leaky(float x) { return x > 0.f ? x : NEG * x; }

// ---------------- fused edge softmax + aggregate + ELU (warp per node) -------
__global__ void edge128_kernel(const float* __restrict__ feat,
                               float* __restrict__ hout) {
    int node = (blockIdx.x * blockDim.x + threadIdx.x) >> 5;
    int lane = threadIdx.x & 31;
    if (node >= N_NODES) return;
    int beg = g_off[node], end = g_off[node + 1];

    float4 er0 = ((const float4*)g_er)[node * 2];
    float4 er1 = ((const float4*)g_er)[node * 2 + 1];

    float m[8];
    #pragma unroll
    for (int h = 0; h < 8; h++) m[h] = -3.4e38f;

    for (int j = beg + lane; j < end; j += 32) {
        int s = g_ssrc[j];
        float4 e0 = ((const float4*)g_el)[s * 2];
        float4 e1 = ((const float4*)g_el)[s * 2 + 1];
        m[0] = fmaxf(m[0], leaky(e0.x + er0.x));
        m[1] = fmaxf(m[1], leaky(e0.y + er0.y));
        m[2] = fmaxf(m[2], leaky(e0.z + er0.z));
        m[3] = fmaxf(m[3], leaky(e0.w + er0.w));
        m[4] = fmaxf(m[4], leaky(e1.x + er1.x));
        m[5] = fmaxf(m[5], leaky(e1.y + er1.y));
        m[6] = fmaxf(m[6], leaky(e1.z + er1.z));
        m[7] = fmaxf(m[7], leaky(e1.w + er1.w));
    }
    #pragma unroll
    for (int h = 0; h < 8; h++) {
        #pragma unroll
        for (int d = 16; d >= 1; d >>= 1)
            m[h] = fmaxf(m[h], __shfl_xor_sync(0xffffffffu, m[h], d));
    }

    int head = lane >> 2;
    float emaxh = m[0];
    if (head == 1) emaxh = m[1];
    if (head == 2) emaxh = m[2];
    if (head == 3) emaxh = m[3];
    if (head == 4) emaxh = m[4];
    if (head == 5) emaxh = m[5];
    if (head == 6) emaxh = m[6];
    if (head == 7) emaxh = m[7];
    float erh = er0.x;
    if (head == 1) erh = er0.y;
    if (head == 2) erh = er0.z;
    if (head == 3) erh = er0.w;
    if (head == 4) erh = er1.x;
    if (head == 5) erh = er1.y;
    if (head == 6) erh = er1.z;
    if (head == 7) erh = er1.w;

    float4 acc = make_float4(0.f, 0.f, 0.f, 0.f);
    float den = 0.f;   // identical across the 4 lanes of each head
    for (int j = beg; j < end; j++) {
        int s = g_ssrc[j];
        float e = leaky(g_el[s * 8 + head] + erh);
        float ex = __expf(e - emaxh);
        float4 f = ((const float4*)feat)[s * 32 + lane];
        acc.x += f.x * ex;
        acc.y += f.y * ex;
        acc.z += f.z * ex;
        acc.w += f.w * ex;
        den += ex;
    }

    float4 o = make_float4(0.f, 0.f, 0.f, 0.f);
    if (den > 0.f) {
        o.x = acc.x / den; o.y = acc.y / den; o.z = acc.z / den; o.w = acc.w / den;
        o.x = o.x > 0.f ? o.x : expm1f(o.x);
        o.y = o.y > 0.f ? o.y : expm1f(o.y);
        o.z = o.z > 0.f ? o.z : expm1f(o.z);
        o.w = o.w > 0.f ? o.w : expm1f(o.w);
    }
    ((float4*)hout)[node * 32 + lane] = o;
}

// ---------------- final layer: GEMM (N,128)@(128,10) + el/er -----------------
__global__ void gemm10_kernel(const float* __restrict__ hin,
                              const float* __restrict__ W,
                              const float* __restrict__ al,
                              const float* __restrict__ ar) {
    __shared__ float Ws[128 * NCLS];
    int tid = threadIdx.x;
    for (int i = tid; i < 128 * NCLS; i += blockDim.x) Ws[i] = W[i];
    __syncthreads();
    int node = (blockIdx.x * blockDim.x + tid) >> 5;
    int lane = tid & 31;
    if (node >= N_NODES) return;
    float acc[NCLS];
    #pragma unroll
    for (int c = 0; c < NCLS; c++) acc[c] = 0.f;
    #pragma unroll
    for (int c4 = 0; c4 < 4; c4++) {
        int k = c4 * 32 + lane;
        float hv = hin[node * 128 + k];
        #pragma unroll
        for (int c = 0; c < NCLS; c++) acc[c] += hv * Ws[k * NCLS + c];
    }
    #pragma unroll
    for (int c = 0; c < NCLS; c++) {
        #pragma unroll
        for (int d = 16; d >= 1; d >>= 1)
            acc[c] += __shfl_xor_sync(0xffffffffu, acc[c], d);
    }
    if (lane == 0) {
        float e_l = 0.f, e_r = 0.f;
        #pragma unroll
        for (int c = 0; c < NCLS; c++) {
            g_feat5[node * NCLS + c] = acc[c];
            e_l += acc[c] * al[c];
            e_r += acc[c] * ar[c];
        }
        g_el5[node] = e_l;
        g_er5[node] = e_r;
    }
}

__global__ void edge10_kernel(float* __restrict__ out) {
    int node = (blockIdx.x * blockDim.x + threadIdx.x) >> 5;
    int lane = threadIdx.x & 31;
    if (node >= N_NODES) return;
    int beg = g_off[node], end = g_off[node + 1];
    float ern = g_er5[node];
    float m = -3.4e38f;
    for (int j = beg + lane; j < end; j += 32) {
        int s = g_ssrc[j];
        m = fmaxf(m, leaky(g_el5[s] + ern));
    }
    #pragma unroll
    for (int d = 16; d >= 1; d >>= 1)
        m = fmaxf(m, __shfl_xor_sync(0xffffffffu, m, d));
    float acc = 0.f, den = 0.f;
    for (int j = beg; j < end; j++) {
        int s = g_ssrc[j];
        float ex = __expf(leaky(g_el5[s] + ern) - m);
        den += ex;
        if (lane < NCLS) acc += g_feat5[s * NCLS + lane] * ex;
    }
    if (lane < NCLS) out[node * NCLS + lane] = den > 0.f ? acc / den : 0.f;
}

// ---------------- launch -----------------------------------------------------
extern "C" void kernel_launch(void* const* d_in, const int* in_sizes, int n_in,
                              void* d_out, int out_size) {
    const float* h   = (const float*)d_in[0];
    const int*   src = (const int*)d_in[1];
    const int*   dst = (const int*)d_in[2];
    const float* W[5]; const float* al[5]; const float* ar[5];
    for (int i = 0; i < 5; i++) {
        W[i]  = (const float*)d_in[3 + 3 * i];
        al[i] = (const float*)d_in[4 + 3 * i];
        ar[i] = (const float*)d_in[5 + 3 * i];
    }

    float *feat, *hA, *hB;
    cudaGetSymbolAddress((void**)&feat, g_feat);
    cudaGetSymbolAddress((void**)&hA, g_hA);
    cudaGetSymbolAddress((void**)&hB, g_hB);

    const int smem_gemm = (128 * 128 + 64 * 128) * (int)sizeof(float); // 96KB
    cudaFuncSetAttribute(gemm128_kernel,
                         cudaFuncAttributeMaxDynamicSharedMemorySize, smem_gemm);

    // CSR build
    zero_kernel<<<(N_NODES + 255) / 256, 256>>>();
    count_kernel<<<(N_EDGES + 255) / 256, 256>>>(dst);
    scan_kernel<<<1, 1024>>>();
    scatter_kernel<<<(N_EDGES + 255) / 256, 256>>>(src, dst);

    const int node_warp_grid = (N_NODES * 32 + 255) / 256;  // warp per node, 256 thr
    const float* cur = h;
    float* bufs[2] = { hA, hB };
    for (int L = 0; L < 4; L++) {
        gemm128_kernel<<<(N_NODES + 63) / 64, 256, smem_gemm>>>(cur, W[L], feat);
        elr_kernel<<<node_warp_grid, 256>>>(feat, al[L], ar[L]);
        edge128_kernel<<<node_warp_grid, 256>>>(feat, bufs[L & 1]);
        cur = bufs[L & 1];
    }
    gemm10_kernel<<<node_warp_grid, 256>>>(cur, W[4], al[4], ar[4]);
    edge10_kernel<<<node_warp_grid, 256>>>((float*)d_out);
}

// round 4
// speedup vs baseline: 1.2894x; 1.2894x over previous
#include <cuda_runtime.h>
#include <cuda_fp16.h>
#include <math.h>
#include <cstdint>

#define N_NODES 50000
#define N_EDGES 800000
#define FEA     128      // HEADS*HID
#define HEADS   8
#define NCLS    10
#define NEG     0.2f
#define PAD     132      // smem row pad: bank = (4*row + k) % 32, conflict-free

// ---------------- scratch (device globals: no allocation allowed) ------------
__device__ __half g_feat16[N_NODES * FEA];
__device__ float g_hA[N_NODES * FEA];
__device__ float g_hB[N_NODES * FEA];
__device__ float g_el[N_NODES * HEADS];
__device__ float g_er[N_NODES * HEADS];
__device__ float g_feat5[N_NODES * NCLS];
__device__ float g_el5[N_NODES];
__device__ float g_er5[N_NODES];
__device__ int   g_cnt[N_NODES];
__device__ int   g_cur[N_NODES];
__device__ int   g_off[N_NODES + 1];
__device__ int   g_ssrc[N_EDGES];

// ---------------- CSR build --------------------------------------------------
__global__ void zero_kernel() {
    int i = blockIdx.x * blockDim.x + threadIdx.x;
    if (i < N_NODES) { g_cnt[i] = 0; g_cur[i] = 0; }
}

__global__ void count_kernel(const int* __restrict__ dst) {
    int i = blockIdx.x * blockDim.x + threadIdx.x;
    if (i < N_EDGES) atomicAdd(&g_cnt[dst[i]], 1);
}

__global__ void scan_kernel() {   // single block, 1024 threads
    __shared__ int wsum[32];
    int tid = threadIdx.x, lane = tid & 31, wid = tid >> 5;
    int carry = 0;
    for (int base = 0; base < N_NODES; base += 1024) {
        int i = base + tid;
        int v = (i < N_NODES) ? g_cnt[i] : 0;
        int x = v;
        #pragma unroll
        for (int d = 1; d < 32; d <<= 1) {
            int t = __shfl_up_sync(0xffffffffu, x, d);
            if (lane >= d) x += t;
        }
        if (lane == 31) wsum[wid] = x;
        __syncthreads();
        if (wid == 0) {
            int s = wsum[lane];
            #pragma unroll
            for (int d = 1; d < 32; d <<= 1) {
                int t = __shfl_up_sync(0xffffffffu, s, d);
                if (lane >= d) s += t;
            }
            wsum[lane] = s;
        }
        __syncthreads();
        int pre = (wid > 0) ? wsum[wid - 1] : 0;
        int incl = x + pre;
        if (i < N_NODES) g_off[i] = carry + incl - v;   // exclusive
        carry += wsum[31];
        __syncthreads();
    }
    if (tid == 0) g_off[N_NODES] = carry;
}

__global__ void scatter_kernel(const int* __restrict__ src, const int* __restrict__ dst) {
    int i = blockIdx.x * blockDim.x + threadIdx.x;
    if (i < N_EDGES) {
        int d = dst[i];
        int p = atomicAdd(&g_cur[d], 1);
        g_ssrc[g_off[d] + p] = src[i];
    }
}

// ---------------- 3xTF32 tensor-core GEMM: (N,128)@(128,128) -> half ---------
__device__ __forceinline__ float tf32_rn(float x) {
    uint32_t u;
    asm("cvt.rna.tf32.f32 %0, %1;" : "=r"(u) : "f"(x));
    return __uint_as_float(u);
}

__device__ __forceinline__ void mma_tf32(float* d, const uint32_t* a, const uint32_t* b) {
    asm volatile(
        "mma.sync.aligned.m16n8k8.row.col.f32.tf32.tf32.f32 "
        "{%0,%1,%2,%3}, {%4,%5,%6,%7}, {%8,%9}, {%0,%1,%2,%3};"
        : "+f"(d[0]), "+f"(d[1]), "+f"(d[2]), "+f"(d[3])
        : "r"(a[0]), "r"(a[1]), "r"(a[2]), "r"(a[3]), "r"(b[0]), "r"(b[1]));
}

// 64 rows x 128 cols per block, 256 threads (8 warps in 2x4), warp tile 32x32.
__global__ void gemm128_tc(const float* __restrict__ hin,
                           const float* __restrict__ W,
                           __half* __restrict__ feat16) {
    extern __shared__ float sm[];
    float* Ah = sm;                   // [64][PAD]
    float* Al = Ah + 64 * PAD;
    float* Bh = Al + 64 * PAD;        // [n][k] transposed: [128][PAD]
    float* Bl = Bh + 128 * PAD;
    int tid = threadIdx.x;
    int row0 = blockIdx.x * 64;

    // load + tf32-split W, transposed to [n][k]
    for (int i = tid; i < 128 * 128; i += 256) {
        int k = i >> 7, n = i & 127;
        float v = W[i];
        float hi = tf32_rn(v);
        float lo = tf32_rn(v - hi);
        Bh[n * PAD + k] = hi;
        Bl[n * PAD + k] = lo;
    }
    // load + split A rows
    for (int i = tid; i < 64 * 128; i += 256) {
        int r = i >> 7, k = i & 127;
        int gr = row0 + r;
        float v = (gr < N_NODES) ? hin[gr * 128 + k] : 0.f;
        float hi = tf32_rn(v);
        float lo = tf32_rn(v - hi);
        Ah[r * PAD + k] = hi;
        Al[r * PAD + k] = lo;
    }
    __syncthreads();

    int warp = tid >> 5, lane = tid & 31;
    int wm = warp & 1, wn = warp >> 1;       // 2 x 4 warp grid
    int m0 = wm * 32, n0 = wn * 32;
    int g = lane >> 2, t = lane & 3;

    float acc[2][4][4];
    #pragma unroll
    for (int mt = 0; mt < 2; mt++)
        #pragma unroll
        for (int nt = 0; nt < 4; nt++)
            #pragma unroll
            for (int q = 0; q < 4; q++) acc[mt][nt][q] = 0.f;

    for (int k0 = 0; k0 < 128; k0 += 8) {
        uint32_t a_h[2][4], a_l[2][4];
        #pragma unroll
        for (int mt = 0; mt < 2; mt++) {
            int r = m0 + mt * 16 + g;
            a_h[mt][0] = __float_as_uint(Ah[r * PAD + k0 + t]);
            a_h[mt][1] = __float_as_uint(Ah[(r + 8) * PAD + k0 + t]);
            a_h[mt][2] = __float_as_uint(Ah[r * PAD + k0 + t + 4]);
            a_h[mt][3] = __float_as_uint(Ah[(r + 8) * PAD + k0 + t + 4]);
            a_l[mt][0] = __float_as_uint(Al[r * PAD + k0 + t]);
            a_l[mt][1] = __float_as_uint(Al[(r + 8) * PAD + k0 + t]);
            a_l[mt][2] = __float_as_uint(Al[r * PAD + k0 + t + 4]);
            a_l[mt][3] = __float_as_uint(Al[(r + 8) * PAD + k0 + t + 4]);
        }
        #pragma unroll
        for (int nt = 0; nt < 4; nt++) {
            int n = n0 + nt * 8 + g;
            uint32_t b_h[2], b_l[2];
            b_h[0] = __float_as_uint(Bh[n * PAD + k0 + t]);
            b_h[1] = __float_as_uint(Bh[n * PAD + k0 + t + 4]);
            b_l[0] = __float_as_uint(Bl[n * PAD + k0 + t]);
            b_l[1] = __float_as_uint(Bl[n * PAD + k0 + t + 4]);
            #pragma unroll
            for (int mt = 0; mt < 2; mt++) {
                mma_tf32(acc[mt][nt], a_h[mt], b_h);
                mma_tf32(acc[mt][nt], a_l[mt], b_h);
                mma_tf32(acc[mt][nt], a_h[mt], b_l);
            }
        }
    }

    // epilogue: emit fp16 features
    #pragma unroll
    for (int mt = 0; mt < 2; mt++) {
        #pragma unroll
        for (int nt = 0; nt < 4; nt++) {
            int r = row0 + m0 + mt * 16 + g;
            int c = n0 + nt * 8 + 2 * t;
            if (r < N_NODES) {
                __half2 p = __floats2half2_rn(acc[mt][nt][0], acc[mt][nt][1]);
                *(__half2*)&feat16[(size_t)r * 128 + c] = p;
            }
            if (r + 8 < N_NODES) {
                __half2 p = __floats2half2_rn(acc[mt][nt][2], acc[mt][nt][3]);
                *(__half2*)&feat16[(size_t)(r + 8) * 128 + c] = p;
            }
        }
    }
}

// ---------------- el/er per node (from fp16 feat) ----------------------------
__global__ void elr_kernel(const __half* __restrict__ feat16,
                           const float* __restrict__ al,
                           const float* __restrict__ ar) {
    int node = (blockIdx.x * blockDim.x + threadIdx.x) >> 5;
    int lane = threadIdx.x & 31;
    if (node >= N_NODES) return;
    uint2 raw = *(const uint2*)(feat16 + (size_t)node * 128 + lane * 4);
    float2 f01 = __half22float2(*(__half2*)&raw.x);
    float2 f23 = __half22float2(*(__half2*)&raw.y);
    float4 a = ((const float4*)al)[lane];
    float4 b = ((const float4*)ar)[lane];
    float pl = f01.x * a.x + f01.y * a.y + f23.x * a.z + f23.y * a.w;
    float pr = f01.x * b.x + f01.y * b.y + f23.x * b.z + f23.y * b.w;
    pl += __shfl_xor_sync(0xffffffffu, pl, 1);
    pr += __shfl_xor_sync(0xffffffffu, pr, 1);
    pl += __shfl_xor_sync(0xffffffffu, pl, 2);
    pr += __shfl_xor_sync(0xffffffffu, pr, 2);
    if ((lane & 3) == 0) {
        g_el[node * 8 + (lane >> 2)] = pl;
        g_er[node * 8 + (lane >> 2)] = pr;
    }
}

__device__ __forceinline__ float leaky(float x) { return x > 0.f ? x : NEG * x; }

// ---------------- fused edge softmax + aggregate + ELU (warp per node) -------
__global__ void edge128_kernel(const __half* __restrict__ feat16,
                               float* __restrict__ hout) {
    int node = (blockIdx.x * blockDim.x + threadIdx.x) >> 5;
    int lane = threadIdx.x & 31;
    if (node >= N_NODES) return;
    int beg = g_off[node], end = g_off[node + 1];

    float4 er0 = ((const float4*)g_er)[node * 2];
    float4 er1 = ((const float4*)g_er)[node * 2 + 1];

    float m[8];
    #pragma unroll
    for (int h = 0; h < 8; h++) m[h] = -3.4e38f;

    for (int j = beg + lane; j < end; j += 32) {
        int s = g_ssrc[j];
        float4 e0 = ((const float4*)g_el)[s * 2];
        float4 e1 = ((const float4*)g_el)[s * 2 + 1];
        m[0] = fmaxf(m[0], leaky(e0.x + er0.x));
        m[1] = fmaxf(m[1], leaky(e0.y + er0.y));
        m[2] = fmaxf(m[2], leaky(e0.z + er0.z));
        m[3] = fmaxf(m[3], leaky(e0.w + er0.w));
        m[4] = fmaxf(m[4], leaky(e1.x + er1.x));
        m[5] = fmaxf(m[5], leaky(e1.y + er1.y));
        m[6] = fmaxf(m[6], leaky(e1.z + er1.z));
        m[7] = fmaxf(m[7], leaky(e1.w + er1.w));
    }
    #pragma unroll
    for (int h = 0; h < 8; h++) {
        #pragma unroll
        for (int d = 16; d >= 1; d >>= 1)
            m[h] = fmaxf(m[h], __shfl_xor_sync(0xffffffffu, m[h], d));
    }

    int head = lane >> 2;
    float emaxh = m[0];
    if (head == 1) emaxh = m[1];
    if (head == 2) emaxh = m[2];
    if (head == 3) emaxh = m[3];
    if (head == 4) emaxh = m[4];
    if (head == 5) emaxh = m[5];
    if (head == 6) emaxh = m[6];
    if (head == 7) emaxh = m[7];
    float erh = er0.x;
    if (head == 1) erh = er0.y;
    if (head == 2) erh = er0.z;
    if (head == 3) erh = er0.w;
    if (head == 4) erh = er1.x;
    if (head == 5) erh = er1.y;
    if (head == 6) erh = er1.z;
    if (head == 7) erh = er1.w;

    float4 acc = make_float4(0.f, 0.f, 0.f, 0.f);
    float den = 0.f;   // identical across the 4 lanes of each head
    #pragma unroll 2
    for (int j = beg; j < end; j++) {
        int s = g_ssrc[j];
        float e = leaky(g_el[s * 8 + head] + erh);
        float ex = __expf(e - emaxh);
        uint2 raw = *(const uint2*)(feat16 + (size_t)s * 128 + lane * 4);
        float2 f01 = __half22float2(*(__half2*)&raw.x);
        float2 f23 = __half22float2(*(__half2*)&raw.y);
        acc.x += f01.x * ex;
        acc.y += f01.y * ex;
        acc.z += f23.x * ex;
        acc.w += f23.y * ex;
        den += ex;
    }

    float4 o = make_float4(0.f, 0.f, 0.f, 0.f);
    if (den > 0.f) {
        o.x = acc.x / den; o.y = acc.y / den; o.z = acc.z / den; o.w = acc.w / den;
        o.x = o.x > 0.f ? o.x : expm1f(o.x);
        o.y = o.y > 0.f ? o.y : expm1f(o.y);
        o.z = o.z > 0.f ? o.z : expm1f(o.z);
        o.w = o.w > 0.f ? o.w : expm1f(o.w);
    }
    ((float4*)hout)[node * 32 + lane] = o;
}

// ---------------- final layer: GEMM (N,128)@(128,10) + el/er -----------------
__global__ void gemm10_kernel(const float* __restrict__ hin,
                              const float* __restrict__ W,
                              const float* __restrict__ al,
                              const float* __restrict__ ar) {
    __shared__ float Ws[128 * NCLS];
    int tid = threadIdx.x;
    for (int i = tid; i < 128 * NCLS; i += blockDim.x) Ws[i] = W[i];
    __syncthreads();
    int node = (blockIdx.x * blockDim.x + tid) >> 5;
    int lane = tid & 31;
    if (node >= N_NODES) return;
    float acc[NCLS];
    #pragma unroll
    for (int c = 0; c < NCLS; c++) acc[c] = 0.f;
    #pragma unroll
    for (int c4 = 0; c4 < 4; c4++) {
        int k = c4 * 32 + lane;
        float hv = hin[node * 128 + k];
        #pragma unroll
        for (int c = 0; c < NCLS; c++) acc[c] += hv * Ws[k * NCLS + c];
    }
    #pragma unroll
    for (int c = 0; c < NCLS; c++) {
        #pragma unroll
        for (int d = 16; d >= 1; d >>= 1)
            acc[c] += __shfl_xor_sync(0xffffffffu, acc[c], d);
    }
    if (lane == 0) {
        float e_l = 0.f, e_r = 0.f;
        #pragma unroll
        for (int c = 0; c < NCLS; c++) {
            g_feat5[node * NCLS + c] = acc[c];
            e_l += acc[c] * al[c];
            e_r += acc[c] * ar[c];
        }
        g_el5[node] = e_l;
        g_er5[node] = e_r;
    }
}

__global__ void edge10_kernel(float* __restrict__ out) {
    int node = (blockIdx.x * blockDim.x + threadIdx.x) >> 5;
    int lane = threadIdx.x & 31;
    if (node >= N_NODES) return;
    int beg = g_off[node], end = g_off[node + 1];
    float ern = g_er5[node];
    float m = -3.4e38f;
    for (int j = beg + lane; j < end; j += 32) {
        int s = g_ssrc[j];
        m = fmaxf(m, leaky(g_el5[s] + ern));
    }
    #pragma unroll
    for (int d = 16; d >= 1; d >>= 1)
        m = fmaxf(m, __shfl_xor_sync(0xffffffffu, m, d));
    float acc = 0.f, den = 0.f;
    for (int j = beg; j < end; j++) {
        int s = g_ssrc[j];
        float ex = __expf(leaky(g_el5[s] + ern) - m);
        den += ex;
        if (lane < NCLS) acc += g_feat5[s * NCLS + lane] * ex;
    }
    if (lane < NCLS) out[node * NCLS + lane] = den > 0.f ? acc / den : 0.f;
}

// ---------------- launch -----------------------------------------------------
extern "C" void kernel_launch(void* const* d_in, const int* in_sizes, int n_in,
                              void* d_out, int out_size) {
    const float* h   = (const float*)d_in[0];
    const int*   src = (const int*)d_in[1];
    const int*   dst = (const int*)d_in[2];
    const float* W[5]; const float* al[5]; const float* ar[5];
    for (int i = 0; i < 5; i++) {
        W[i]  = (const float*)d_in[3 + 3 * i];
        al[i] = (const float*)d_in[4 + 3 * i];
        ar[i] = (const float*)d_in[5 + 3 * i];
    }

    __half* feat16;
    float *hA, *hB;
    cudaGetSymbolAddress((void**)&feat16, g_feat16);
    cudaGetSymbolAddress((void**)&hA, g_hA);
    cudaGetSymbolAddress((void**)&hB, g_hB);

    const int smem_tc = (64 * PAD * 2 + 128 * PAD * 2) * (int)sizeof(float); // 202752
    static bool s_init = false;
    static cudaStream_t s_csr;
    static cudaEvent_t ev_fork, ev_join;
    if (!s_init) {
        cudaFuncSetAttribute(gemm128_tc,
                             cudaFuncAttributeMaxDynamicSharedMemorySize, smem_tc);
        cudaStreamCreateWithFlags(&s_csr, cudaStreamNonBlocking);
        cudaEventCreateWithFlags(&ev_fork, cudaEventDisableTiming);
        cudaEventCreateWithFlags(&ev_join, cudaEventDisableTiming);
        s_init = true;
    }

    // ---- fork: CSR build on side stream, overlapped with layer-0 GEMM ----
    cudaEventRecord(ev_fork, 0);
    cudaStreamWaitEvent(s_csr, ev_fork, 0);
    zero_kernel<<<(N_NODES + 255) / 256, 256, 0, s_csr>>>();
    count_kernel<<<(N_EDGES + 255) / 256, 256, 0, s_csr>>>(dst);
    scan_kernel<<<1, 1024, 0, s_csr>>>();
    scatter_kernel<<<(N_EDGES + 255) / 256, 256, 0, s_csr>>>(src, dst);
    cudaEventRecord(ev_join, s_csr);

    const int node_warp_grid = (N_NODES * 32 + 255) / 256;  // warp per node
    const int gemm_grid = (N_NODES + 63) / 64;

    // layer 0 feature path (independent of CSR)
    gemm128_tc<<<gemm_grid, 256, smem_tc>>>(h, W[0], feat16);
    elr_kernel<<<node_warp_grid, 256>>>(feat16, al[0], ar[0]);
    cudaStreamWaitEvent(0, ev_join, 0);   // join before first edge kernel
    edge128_kernel<<<node_warp_grid, 256>>>(feat16, hA);

    const float* cur = hA;
    float* bufs[2] = { hA, hB };
    for (int L = 1; L < 4; L++) {
        gemm128_tc<<<gemm_grid, 256, smem_tc>>>(cur, W[L], feat16);
        elr_kernel<<<node_warp_grid, 256>>>(feat16, al[L], ar[L]);
        edge128_kernel<<<node_warp_grid, 256>>>(feat16, bufs[L & 1]);
        cur = bufs[L & 1];
    }
    gemm10_kernel<<<node_warp_grid, 256>>>(cur, W[4], al[4], ar[4]);
    edge10_kernel<<<node_warp_grid, 256>>>((float*)d_out);
}

// round 5
// speedup vs baseline: 1.4538x; 1.1275x over previous
#include <cuda_runtime.h>
#include <cuda_fp16.h>
#include <math.h>
#include <cstdint>

#define N_NODES 50000
#define N_EDGES 800000
#define FEA     128      // HEADS*HID
#define HEADS   8
#define NCLS    10
#define NEG     0.2f
#define PAD     132      // smem row pad, conflict-free fragment loads

#define SCAN_BLK 1024
#define NPART ((N_NODES + SCAN_BLK - 1) / SCAN_BLK)   // 49

// ---------------- scratch (device globals: no allocation allowed) ------------
__device__ __half g_feat16[N_NODES * FEA];
__device__ __half g_hA[N_NODES * FEA];
__device__ __half g_hB[N_NODES * FEA];
__device__ float g_el[N_NODES * HEADS];
__device__ float g_er[N_NODES * HEADS];
__device__ float g_feat5[N_NODES * NCLS];
__device__ float g_el5[N_NODES];
__device__ float g_er5[N_NODES];
__device__ int   g_cnt[N_NODES];
__device__ int   g_cur[N_NODES];
__device__ int   g_off[N_NODES + 1];
__device__ int   g_part[NPART];
__device__ int   g_ssrc[N_EDGES];

// ---------------- CSR build --------------------------------------------------
__global__ void zero_kernel() {
    int i = blockIdx.x * blockDim.x + threadIdx.x;
    if (i < N_NODES) { g_cnt[i] = 0; g_cur[i] = 0; }
}

__global__ void count_kernel(const int* __restrict__ dst) {
    int i = blockIdx.x * blockDim.x + threadIdx.x;
    if (i < N_EDGES) atomicAdd(&g_cnt[dst[i]], 1);
}

// scan1: per-block inclusive scan of 1024 counts -> local exclusive + block total
__global__ void scan1_kernel() {
    __shared__ int wsum[32];
    int tid = threadIdx.x, lane = tid & 31, wid = tid >> 5;
    int i = blockIdx.x * SCAN_BLK + tid;
    int v = (i < N_NODES) ? g_cnt[i] : 0;
    int x = v;
    #pragma unroll
    for (int d = 1; d < 32; d <<= 1) {
        int t = __shfl_up_sync(0xffffffffu, x, d);
        if (lane >= d) x += t;
    }
    if (lane == 31) wsum[wid] = x;
    __syncthreads();
    if (wid == 0) {
        int s = wsum[lane];
        #pragma unroll
        for (int d = 1; d < 32; d <<= 1) {
            int t = __shfl_up_sync(0xffffffffu, s, d);
            if (lane >= d) s += t;
        }
        wsum[lane] = s;
    }
    __syncthreads();
    int pre = (wid > 0) ? wsum[wid - 1] : 0;
    int incl = x + pre;
    if (i < N_NODES) g_off[i] = incl - v;       // block-local exclusive
    if (tid == SCAN_BLK - 1) g_part[blockIdx.x] = incl;
}

// scan2: serial scan of 49 partials (single thread; trivial)
__global__ void scan2_kernel() {
    __shared__ int sp[NPART];
    int tid = threadIdx.x;
    if (tid < NPART) sp[tid] = g_part[tid];
    __syncthreads();
    if (tid == 0) {
        int run = 0;
        for (int k = 0; k < NPART; k++) { int t = sp[k]; sp[k] = run; run += t; }
        g_off[N_NODES] = run;
    }
    __syncthreads();
    if (tid < NPART) g_part[tid] = sp[tid];
}

__global__ void scan3_kernel() {
    int i = blockIdx.x * blockDim.x + threadIdx.x;
    if (i < N_NODES) g_off[i] += g_part[i / SCAN_BLK];
}

__global__ void scatter_kernel(const int* __restrict__ src, const int* __restrict__ dst) {
    int i = blockIdx.x * blockDim.x + threadIdx.x;
    if (i < N_EDGES) {
        int d = dst[i];
        int p = atomicAdd(&g_cur[d], 1);
        g_ssrc[g_off[d] + p] = src[i];
    }
}

// ---------------- 3xTF32 tensor-core GEMM: (N,128)@(128,128) -> half ---------
__device__ __forceinline__ float tf32_rn(float x) {
    uint32_t u;
    asm("cvt.rna.tf32.f32 %0, %1;" : "=r"(u) : "f"(x));
    return __uint_as_float(u);
}

__device__ __forceinline__ float ld_f32(const float* p)  { return *p; }
__device__ __forceinline__ float ld_f32(const __half* p) { return __half2float(*p); }

__device__ __forceinline__ void mma_tf32(float* d, const uint32_t* a, const uint32_t* b) {
    asm volatile(
        "mma.sync.aligned.m16n8k8.row.col.f32.tf32.tf32.f32 "
        "{%0,%1,%2,%3}, {%4,%5,%6,%7}, {%8,%9}, {%0,%1,%2,%3};"
        : "+f"(d[0]), "+f"(d[1]), "+f"(d[2]), "+f"(d[3])
        : "r"(a[0]), "r"(a[1]), "r"(a[2]), "r"(a[3]), "r"(b[0]), "r"(b[1]));
}

// 64 rows x 128 cols per block, 256 threads (8 warps in 2x4), warp tile 32x32.
template <typename TIN>
__global__ void gemm128_tc(const TIN* __restrict__ hin,
                           const float* __restrict__ W,
                           __half* __restrict__ feat16) {
    extern __shared__ float sm[];
    float* Ah = sm;                   // [64][PAD]
    float* Al = Ah + 64 * PAD;
    float* Bh = Al + 64 * PAD;        // [n][k] transposed: [128][PAD]
    float* Bl = Bh + 128 * PAD;
    int tid = threadIdx.x;
    int row0 = blockIdx.x * 64;

    // load + tf32-split W, transposed to [n][k]
    for (int i = tid; i < 128 * 128; i += 256) {
        int k = i >> 7, n = i & 127;
        float v = W[i];
        float hi = tf32_rn(v);
        float lo = tf32_rn(v - hi);
        Bh[n * PAD + k] = hi;
        Bl[n * PAD + k] = lo;
    }
    // load + split A rows
    for (int i = tid; i < 64 * 128; i += 256) {
        int r = i >> 7, k = i & 127;
        int gr = row0 + r;
        float v = (gr < N_NODES) ? ld_f32(&hin[(size_t)gr * 128 + k]) : 0.f;
        float hi = tf32_rn(v);
        float lo = tf32_rn(v - hi);
        Ah[r * PAD + k] = hi;
        Al[r * PAD + k] = lo;
    }
    __syncthreads();

    int warp = tid >> 5, lane = tid & 31;
    int wm = warp & 1, wn = warp >> 1;       // 2 x 4 warp grid
    int m0 = wm * 32, n0 = wn * 32;
    int g = lane >> 2, t = lane & 3;

    float acc[2][4][4];
    #pragma unroll
    for (int mt = 0; mt < 2; mt++)
        #pragma unroll
        for (int nt = 0; nt < 4; nt++)
            #pragma unroll
            for (int q = 0; q < 4; q++) acc[mt][nt][q] = 0.f;

    for (int k0 = 0; k0 < 128; k0 += 8) {
        uint32_t a_h[2][4], a_l[2][4];
        #pragma unroll
        for (int mt = 0; mt < 2; mt++) {
            int r = m0 + mt * 16 + g;
            a_h[mt][0] = __float_as_uint(Ah[r * PAD + k0 + t]);
            a_h[mt][1] = __float_as_uint(Ah[(r + 8) * PAD + k0 + t]);
            a_h[mt][2] = __float_as_uint(Ah[r * PAD + k0 + t + 4]);
            a_h[mt][3] = __float_as_uint(Ah[(r + 8) * PAD + k0 + t + 4]);
            a_l[mt][0] = __float_as_uint(Al[r * PAD + k0 + t]);
            a_l[mt][1] = __float_as_uint(Al[(r + 8) * PAD + k0 + t]);
            a_l[mt][2] = __float_as_uint(Al[r * PAD + k0 + t + 4]);
            a_l[mt][3] = __float_as_uint(Al[(r + 8) * PAD + k0 + t + 4]);
        }
        #pragma unroll
        for (int nt = 0; nt < 4; nt++) {
            int n = n0 + nt * 8 + g;
            uint32_t b_h[2], b_l[2];
            b_h[0] = __float_as_uint(Bh[n * PAD + k0 + t]);
            b_h[1] = __float_as_uint(Bh[n * PAD + k0 + t + 4]);
            b_l[0] = __float_as_uint(Bl[n * PAD + k0 + t]);
            b_l[1] = __float_as_uint(Bl[n * PAD + k0 + t + 4]);
            #pragma unroll
            for (int mt = 0; mt < 2; mt++) {
                mma_tf32(acc[mt][nt], a_h[mt], b_h);
                mma_tf32(acc[mt][nt], a_l[mt], b_h);
                mma_tf32(acc[mt][nt], a_h[mt], b_l);
            }
        }
    }

    // epilogue: emit fp16 features
    #pragma unroll
    for (int mt = 0; mt < 2; mt++) {
        #pragma unroll
        for (int nt = 0; nt < 4; nt++) {
            int r = row0 + m0 + mt * 16 + g;
            int c = n0 + nt * 8 + 2 * t;
            if (r < N_NODES) {
                __half2 p = __floats2half2_rn(acc[mt][nt][0], acc[mt][nt][1]);
                *(__half2*)&feat16[(size_t)r * 128 + c] = p;
            }
            if (r + 8 < N_NODES) {
                __half2 p = __floats2half2_rn(acc[mt][nt][2], acc[mt][nt][3]);
                *(__half2*)&feat16[(size_t)(r + 8) * 128 + c] = p;
            }
        }
    }
}

// ---------------- el/er per node (from fp16 feat) ----------------------------
__global__ void elr_kernel(const __half* __restrict__ feat16,
                           const float* __restrict__ al,
                           const float* __restrict__ ar) {
    int node = (blockIdx.x * blockDim.x + threadIdx.x) >> 5;
    int lane = threadIdx.x & 31;
    if (node >= N_NODES) return;
    uint2 raw = *(const uint2*)(feat16 + (size_t)node * 128 + lane * 4);
    float2 f01 = __half22float2(*(__half2*)&raw.x);
    float2 f23 = __half22float2(*(__half2*)&raw.y);
    float4 a = ((const float4*)al)[lane];
    float4 b = ((const float4*)ar)[lane];
    float pl = f01.x * a.x + f01.y * a.y + f23.x * a.z + f23.y * a.w;
    float pr = f01.x * b.x + f01.y * b.y + f23.x * b.z + f23.y * b.w;
    pl += __shfl_xor_sync(0xffffffffu, pl, 1);
    pr += __shfl_xor_sync(0xffffffffu, pr, 1);
    pl += __shfl_xor_sync(0xffffffffu, pl, 2);
    pr += __shfl_xor_sync(0xffffffffu, pr, 2);
    if ((lane & 3) == 0) {
        g_el[node * 8 + (lane >> 2)] = pl;
        g_er[node * 8 + (lane >> 2)] = pr;
    }
}

__device__ __forceinline__ float leaky(float x) { return x > 0.f ? x : NEG * x; }

// ---------------- fused edge softmax + aggregate + ELU (warp per node) -------
// Softmax is shift-invariant: skip the max pass (exp args bounded ~|8|).
__global__ void edge128_kernel(const __half* __restrict__ feat16,
                               __half* __restrict__ hout) {
    int node = (blockIdx.x * blockDim.x + threadIdx.x) >> 5;
    int lane = threadIdx.x & 31;
    if (node >= N_NODES) return;
    int beg = g_off[node], end = g_off[node + 1];
    int head = lane >> 2;
    float erh = g_er[node * 8 + head];

    float4 acc = make_float4(0.f, 0.f, 0.f, 0.f);
    float den = 0.f;
    int j = beg;
    for (; j + 4 <= end; j += 4) {
        int s0 = g_ssrc[j], s1 = g_ssrc[j + 1], s2 = g_ssrc[j + 2], s3 = g_ssrc[j + 3];
        float w0 = __expf(leaky(g_el[s0 * 8 + head] + erh));
        float w1 = __expf(leaky(g_el[s1 * 8 + head] + erh));
        float w2 = __expf(leaky(g_el[s2 * 8 + head] + erh));
        float w3 = __expf(leaky(g_el[s3 * 8 + head] + erh));
        uint2 r0 = *(const uint2*)(feat16 + (size_t)s0 * 128 + lane * 4);
        uint2 r1 = *(const uint2*)(feat16 + (size_t)s1 * 128 + lane * 4);
        uint2 r2 = *(const uint2*)(feat16 + (size_t)s2 * 128 + lane * 4);
        uint2 r3 = *(const uint2*)(feat16 + (size_t)s3 * 128 + lane * 4);
        {
            float2 a01 = __half22float2(*(__half2*)&r0.x);
            float2 a23 = __half22float2(*(__half2*)&r0.y);
            acc.x += a01.x * w0; acc.y += a01.y * w0;
            acc.z += a23.x * w0; acc.w += a23.y * w0;
        }
        {
            float2 a01 = __half22float2(*(__half2*)&r1.x);
            float2 a23 = __half22float2(*(__half2*)&r1.y);
            acc.x += a01.x * w1; acc.y += a01.y * w1;
            acc.z += a23.x * w1; acc.w += a23.y * w1;
        }
        {
            float2 a01 = __half22float2(*(__half2*)&r2.x);
            float2 a23 = __half22float2(*(__half2*)&r2.y);
            acc.x += a01.x * w2; acc.y += a01.y * w2;
            acc.z += a23.x * w2; acc.w += a23.y * w2;
        }
        {
            float2 a01 = __half22float2(*(__half2*)&r3.x);
            float2 a23 = __half22float2(*(__half2*)&r3.y);
            acc.x += a01.x * w3; acc.y += a01.y * w3;
            acc.z += a23.x * w3; acc.w += a23.y * w3;
        }
        den += w0 + w1 + w2 + w3;
    }
    for (; j < end; j++) {
        int s = g_ssrc[j];
        float w = __expf(leaky(g_el[s * 8 + head] + erh));
        uint2 r = *(const uint2*)(feat16 + (size_t)s * 128 + lane * 4);
        float2 a01 = __half22float2(*(__half2*)&r.x);
        float2 a23 = __half22float2(*(__half2*)&r.y);
        acc.x += a01.x * w; acc.y += a01.y * w;
        acc.z += a23.x * w; acc.w += a23.y * w;
        den += w;
    }

    float4 o = make_float4(0.f, 0.f, 0.f, 0.f);
    if (den > 0.f) {
        float inv = 1.f / den;
        o.x = acc.x * inv; o.y = acc.y * inv; o.z = acc.z * inv; o.w = acc.w * inv;
        o.x = o.x > 0.f ? o.x : expm1f(o.x);
        o.y = o.y > 0.f ? o.y : expm1f(o.y);
        o.z = o.z > 0.f ? o.z : expm1f(o.z);
        o.w = o.w > 0.f ? o.w : expm1f(o.w);
    }
    uint2 st;
    *(__half2*)&st.x = __floats2half2_rn(o.x, o.y);
    *(__half2*)&st.y = __floats2half2_rn(o.z, o.w);
    *(uint2*)(hout + (size_t)node * 128 + lane * 4) = st;
}

// ---------------- final layer: GEMM (N,128)@(128,10) + el/er -----------------
__global__ void gemm10_kernel(const __half* __restrict__ hin,
                              const float* __restrict__ W,
                              const float* __restrict__ al,
                              const float* __restrict__ ar) {
    __shared__ float Ws[128 * NCLS];
    int tid = threadIdx.x;
    for (int i = tid; i < 128 * NCLS; i += blockDim.x) Ws[i] = W[i];
    __syncthreads();
    int node = (blockIdx.x * blockDim.x + tid) >> 5;
    int lane = tid & 31;
    if (node >= N_NODES) return;
    float acc[NCLS];
    #pragma unroll
    for (int c = 0; c < NCLS; c++) acc[c] = 0.f;
    #pragma unroll
    for (int c4 = 0; c4 < 4; c4++) {
        int k = c4 * 32 + lane;
        float hv = __half2float(hin[(size_t)node * 128 + k]);
        #pragma unroll
        for (int c = 0; c < NCLS; c++) acc[c] += hv * Ws[k * NCLS + c];
    }
    #pragma unroll
    for (int c = 0; c < NCLS; c++) {
        #pragma unroll
        for (int d = 16; d >= 1; d >>= 1)
            acc[c] += __shfl_xor_sync(0xffffffffu, acc[c], d);
    }
    if (lane == 0) {
        float e_l = 0.f, e_r = 0.f;
        #pragma unroll
        for (int c = 0; c < NCLS; c++) {
            g_feat5[node * NCLS + c] = acc[c];
            e_l += acc[c] * al[c];
            e_r += acc[c] * ar[c];
        }
        g_el5[node] = e_l;
        g_er5[node] = e_r;
    }
}

__global__ void edge10_kernel(float* __restrict__ out) {
    int node = (blockIdx.x * blockDim.x + threadIdx.x) >> 5;
    int lane = threadIdx.x & 31;
    if (node >= N_NODES) return;
    int beg = g_off[node], end = g_off[node + 1];
    float ern = g_er5[node];
    float acc = 0.f, den = 0.f;
    for (int j = beg; j < end; j++) {
        int s = g_ssrc[j];
        float ex = __expf(leaky(g_el5[s] + ern));
        den += ex;
        if (lane < NCLS) acc += g_feat5[s * NCLS + lane] * ex;
    }
    if (lane < NCLS) out[node * NCLS + lane] = den > 0.f ? acc / den : 0.f;
}

// ---------------- launch -----------------------------------------------------
extern "C" void kernel_launch(void* const* d_in, const int* in_sizes, int n_in,
                              void* d_out, int out_size) {
    const float* h   = (const float*)d_in[0];
    const int*   src = (const int*)d_in[1];
    const int*   dst = (const int*)d_in[2];
    const float* W[5]; const float* al[5]; const float* ar[5];
    for (int i = 0; i < 5; i++) {
        W[i]  = (const float*)d_in[3 + 3 * i];
        al[i] = (const float*)d_in[4 + 3 * i];
        ar[i] = (const float*)d_in[5 + 3 * i];
    }

    __half *feat16, *hA, *hB;
    cudaGetSymbolAddress((void**)&feat16, g_feat16);
    cudaGetSymbolAddress((void**)&hA, g_hA);
    cudaGetSymbolAddress((void**)&hB, g_hB);

    const int smem_tc = (64 * PAD * 2 + 128 * PAD * 2) * (int)sizeof(float); // 202752
    static bool s_init = false;
    static cudaStream_t s_csr;
    static cudaEvent_t ev_fork, ev_join;
    if (!s_init) {
        cudaFuncSetAttribute(gemm128_tc<float>,
                             cudaFuncAttributeMaxDynamicSharedMemorySize, smem_tc);
        cudaFuncSetAttribute(gemm128_tc<__half>,
                             cudaFuncAttributeMaxDynamicSharedMemorySize, smem_tc);
        cudaStreamCreateWithFlags(&s_csr, cudaStreamNonBlocking);
        cudaEventCreateWithFlags(&ev_fork, cudaEventDisableTiming);
        cudaEventCreateWithFlags(&ev_join, cudaEventDisableTiming);
        s_init = true;
    }

    // ---- fork: CSR build on side stream, overlapped with layer-0 GEMM ----
    cudaEventRecord(ev_fork, 0);
    cudaStreamWaitEvent(s_csr, ev_fork, 0);
    zero_kernel<<<(N_NODES + 255) / 256, 256, 0, s_csr>>>();
    count_kernel<<<(N_EDGES + 255) / 256, 256, 0, s_csr>>>(dst);
    scan1_kernel<<<NPART, SCAN_BLK, 0, s_csr>>>();
    scan2_kernel<<<1, 64, 0, s_csr>>>();
    scan3_kernel<<<(N_NODES + 255) / 256, 256, 0, s_csr>>>();
    scatter_kernel<<<(N_EDGES + 255) / 256, 256, 0, s_csr>>>(src, dst);
    cudaEventRecord(ev_join, s_csr);

    const int node_warp_grid = (N_NODES * 32 + 255) / 256;  // warp per node
    const int gemm_grid = (N_NODES + 63) / 64;

    // layer 0 feature path (independent of CSR)
    gemm128_tc<float><<<gemm_grid, 256, smem_tc>>>(h, W[0], feat16);
    elr_kernel<<<node_warp_grid, 256>>>(feat16, al[0], ar[0]);
    cudaStreamWaitEvent(0, ev_join, 0);   // join before first edge kernel
    edge128_kernel<<<node_warp_grid, 256>>>(feat16, hA);

    const __half* cur = hA;
    __half* bufs[2] = { hA, hB };
    for (int L = 1; L < 4; L++) {
        gemm128_tc<__half><<<gemm_grid, 256, smem_tc>>>(cur, W[L], feat16);
        elr_kernel<<<node_warp_grid, 256>>>(feat16, al[L], ar[L]);
        edge128_kernel<<<node_warp_grid, 256>>>(feat16, bufs[L & 1]);
        cur = bufs[L & 1];
    }
    gemm10_kernel<<<node_warp_grid, 256>>>(cur, W[4], al[4], ar[4]);
    edge10_kernel<<<node_warp_grid, 256>>>((float*)d_out);
}

// round 6
// speedup vs baseline: 2.6207x; 1.8027x over previous
#include <cuda_runtime.h>
#include <cuda_fp16.h>
#include <math.h>
#include <cstdint>

#define N_NODES 50000
#define N_EDGES 800000
#define FEA     128      // HEADS*HID
#define HEADS   8
#define NCLS    10
#define NEG     0.2f
#define PADH    136      // smem row stride in halves; conflict-free fragment loads

#define SCAN_BLK 1024
#define NPART ((N_NODES + SCAN_BLK - 1) / SCAN_BLK)   // 49

// ---------------- scratch (device globals: no allocation allowed) ------------
__device__ __half g_feat16[N_NODES * FEA];
__device__ __half g_hA[N_NODES * FEA];
__device__ __half g_hB[N_NODES * FEA];
__device__ __half g_Whi[4 * FEA * FEA];   // pre-split W, transposed [n][k]
__device__ __half g_Wlo[4 * FEA * FEA];
__device__ float g_el[N_NODES * HEADS];
__device__ float g_er[N_NODES * HEADS];
__device__ float g_feat5[N_NODES * NCLS];
__device__ float g_el5[N_NODES];
__device__ float g_er5[N_NODES];
__device__ int   g_cnt[N_NODES];
__device__ int   g_cur[N_NODES];
__device__ int   g_off[N_NODES + 1];
__device__ int   g_part[NPART];
__device__ int   g_ssrc[N_EDGES];

// ---------------- CSR build --------------------------------------------------
__global__ void zero_kernel() {
    int i = blockIdx.x * blockDim.x + threadIdx.x;
    if (i < N_NODES) g_cnt[i] = 0;
}

__global__ void count_kernel(const int* __restrict__ dst) {
    int i = blockIdx.x * blockDim.x + threadIdx.x;
    if (i < N_EDGES) atomicAdd(&g_cnt[dst[i]], 1);
}

// scan1: per-block inclusive scan -> local exclusive + block total; zero g_cur
__global__ void scan1_kernel() {
    __shared__ int wsum[32];
    int tid = threadIdx.x, lane = tid & 31, wid = tid >> 5;
    int i = blockIdx.x * SCAN_BLK + tid;
    int v = (i < N_NODES) ? g_cnt[i] : 0;
    if (i < N_NODES) g_cur[i] = 0;
    int x = v;
    #pragma unroll
    for (int d = 1; d < 32; d <<= 1) {
        int t = __shfl_up_sync(0xffffffffu, x, d);
        if (lane >= d) x += t;
    }
    if (lane == 31) wsum[wid] = x;
    __syncthreads();
    if (wid == 0) {
        int s = wsum[lane];
        #pragma unroll
        for (int d = 1; d < 32; d <<= 1) {
            int t = __shfl_up_sync(0xffffffffu, s, d);
            if (lane >= d) s += t;
        }
        wsum[lane] = s;
    }
    __syncthreads();
    int pre = (wid > 0) ? wsum[wid - 1] : 0;
    int incl = x + pre;
    if (i < N_NODES) g_off[i] = incl - v;       // block-local exclusive
    if (tid == SCAN_BLK - 1) g_part[blockIdx.x] = incl;
}

// scan3: add prefix of partials (49-iter uniform loop, L1-resident)
__global__ void scan3_kernel() {
    int i = blockIdx.x * blockDim.x + threadIdx.x;
    int part = (blockIdx.x * blockDim.x) / SCAN_BLK;
    int base = 0;
    for (int p = 0; p < part; p++) base += g_part[p];
    if (i < N_NODES) {
        g_off[i] += base;
        if (i == N_NODES - 1) g_off[N_NODES] = g_off[i] + g_cnt[i];
    }
}

__global__ void scatter_kernel(const int* __restrict__ src, const int* __restrict__ dst) {
    int i = blockIdx.x * blockDim.x + threadIdx.x;
    if (i < N_EDGES) {
        int d = dst[i];
        int p = atomicAdd(&g_cur[d], 1);
        g_ssrc[g_off[d] + p] = src[i];
    }
}

// ---------------- W pre-split: fp32 [k][n] -> hi/lo fp16 transposed [n][k] ----
__global__ void wsplit_kernel(const float* __restrict__ W0, const float* __restrict__ W1,
                              const float* __restrict__ W2, const float* __restrict__ W3) {
    int layer = blockIdx.y;
    const float* W = (layer == 0) ? W0 : (layer == 1) ? W1 : (layer == 2) ? W2 : W3;
    int i = blockIdx.x * blockDim.x + threadIdx.x;   // 16384
    int k = i >> 7, n = i & 127;
    float v = W[i];
    __half hi = __float2half_rn(v);
    __half lo = __float2half_rn(v - __half2float(hi));
    g_Whi[layer * FEA * FEA + n * 128 + k] = hi;
    g_Wlo[layer * FEA * FEA + n * 128 + k] = lo;
}

// ---------------- fp16 tensor-core GEMM + fused el/er ------------------------
__device__ __forceinline__ void mma_f16(float* d, const uint32_t* a, const uint32_t* b) {
    asm volatile(
        "mma.sync.aligned.m16n8k16.row.col.f32.f16.f16.f32 "
        "{%0,%1,%2,%3}, {%4,%5,%6,%7}, {%8,%9}, {%0,%1,%2,%3};"
        : "+f"(d[0]), "+f"(d[1]), "+f"(d[2]), "+f"(d[3])
        : "r"(a[0]), "r"(a[1]), "r"(a[2]), "r"(a[3]), "r"(b[0]), "r"(b[1]));
}

__device__ __forceinline__ uint4 ld8h(const float* p) {
    float4 v0 = *(const float4*)p;
    float4 v1 = *(const float4*)(p + 4);
    uint4 r;
    *(__half2*)&r.x = __floats2half2_rn(v0.x, v0.y);
    *(__half2*)&r.y = __floats2half2_rn(v0.z, v0.w);
    *(__half2*)&r.z = __floats2half2_rn(v1.x, v1.y);
    *(__half2*)&r.w = __floats2half2_rn(v1.z, v1.w);
    return r;
}
__device__ __forceinline__ uint4 ld8h(const __half* p) { return *(const uint4*)p; }

__device__ __forceinline__ float qreduce(float v) {   // sum over quad (lanes t=0..3)
    v += __shfl_xor_sync(0xffffffffu, v, 1);
    v += __shfl_xor_sync(0xffffffffu, v, 2);
    return v;
}

// 64 rows x 128 cols per block, 256 threads (8 warps, 2m x 4n), warp tile 32x32.
template <typename TIN>
__global__ __launch_bounds__(256, 2)
void gemm_fp16(const TIN* __restrict__ hin, int layer,
               __half* __restrict__ feat16,
               const float* __restrict__ al, const float* __restrict__ ar) {
    extern __shared__ __half smh[];
    __half* As = smh;                 // [64][PADH]
    __half* Bh = As + 64 * PADH;      // [128][PADH]
    __half* Bl = Bh + 128 * PADH;
    int tid = threadIdx.x;
    int row0 = blockIdx.x * 64;
    const __half* Whi = g_Whi + layer * FEA * FEA;
    const __half* Wlo = g_Wlo + layer * FEA * FEA;

    // A: 64 rows x 16 col-blocks of 8
    #pragma unroll
    for (int it = 0; it < 4; it++) {
        int idx = tid + it * 256;          // 0..1023
        int r = idx >> 4, c8 = (idx & 15) * 8;
        int gr = row0 + r;
        uint4 v = make_uint4(0, 0, 0, 0);
        if (gr < N_NODES) v = ld8h(&hin[(size_t)gr * 128 + c8]);
        *(uint4*)&As[r * PADH + c8] = v;
    }
    // B hi/lo: 128 rows x 16 col-blocks
    #pragma unroll
    for (int it = 0; it < 8; it++) {
        int idx = tid + it * 256;          // 0..2047
        int n = idx >> 4, c8 = (idx & 15) * 8;
        *(uint4*)&Bh[n * PADH + c8] = *(const uint4*)&Whi[n * 128 + c8];
        *(uint4*)&Bl[n * PADH + c8] = *(const uint4*)&Wlo[n * 128 + c8];
    }
    __syncthreads();

    int warp = tid >> 5, lane = tid & 31;
    int wm = warp & 1, wn = warp >> 1;     // 2 x 4 warp grid
    int m0 = wm * 32, n0 = wn * 32;
    int g = lane >> 2, t = lane & 3;

    float acc[2][4][4];
    #pragma unroll
    for (int mt = 0; mt < 2; mt++)
        #pragma unroll
        for (int nt = 0; nt < 4; nt++)
            #pragma unroll
            for (int q = 0; q < 4; q++) acc[mt][nt][q] = 0.f;

    #pragma unroll
    for (int k0 = 0; k0 < 128; k0 += 16) {
        uint32_t a[2][4];
        #pragma unroll
        for (int mt = 0; mt < 2; mt++) {
            int r = m0 + mt * 16 + g;
            a[mt][0] = *(const uint32_t*)&As[r * PADH + k0 + 2 * t];
            a[mt][1] = *(const uint32_t*)&As[(r + 8) * PADH + k0 + 2 * t];
            a[mt][2] = *(const uint32_t*)&As[r * PADH + k0 + 2 * t + 8];
            a[mt][3] = *(const uint32_t*)&As[(r + 8) * PADH + k0 + 2 * t + 8];
        }
        #pragma unroll
        for (int nt = 0; nt < 4; nt++) {
            int n = n0 + nt * 8 + g;
            uint32_t bh[2], bl[2];
            bh[0] = *(const uint32_t*)&Bh[n * PADH + k0 + 2 * t];
            bh[1] = *(const uint32_t*)&Bh[n * PADH + k0 + 2 * t + 8];
            bl[0] = *(const uint32_t*)&Bl[n * PADH + k0 + 2 * t];
            bl[1] = *(const uint32_t*)&Bl[n * PADH + k0 + 2 * t + 8];
            #pragma unroll
            for (int mt = 0; mt < 2; mt++) {
                mma_f16(acc[mt][nt], a[mt], bh);
                mma_f16(acc[mt][nt], a[mt], bl);
            }
        }
    }

    // al/ar values for this thread's 8 columns
    float alv[4][2], arv[4][2];
    #pragma unroll
    for (int nt = 0; nt < 4; nt++) {
        int c = n0 + nt * 8 + 2 * t;
        alv[nt][0] = al[c];     alv[nt][1] = al[c + 1];
        arv[nt][0] = ar[c];     arv[nt][1] = ar[c + 1];
    }

    // epilogue: fp16 feat stores + fused el/er (heads 2wn, 2wn+1 live in this warp)
    #pragma unroll
    for (int mt = 0; mt < 2; mt++) {
        int rA = row0 + m0 + mt * 16 + g;
        int rB = rA + 8;
        float h0lA = 0, h1lA = 0, h0rA = 0, h1rA = 0;
        float h0lB = 0, h1lB = 0, h0rB = 0, h1rB = 0;
        #pragma unroll
        for (int nt = 0; nt < 4; nt++) {
            float pA = acc[mt][nt][0] * alv[nt][0] + acc[mt][nt][1] * alv[nt][1];
            float qA = acc[mt][nt][0] * arv[nt][0] + acc[mt][nt][1] * arv[nt][1];
            float pB = acc[mt][nt][2] * alv[nt][0] + acc[mt][nt][3] * alv[nt][1];
            float qB = acc[mt][nt][2] * arv[nt][0] + acc[mt][nt][3] * arv[nt][1];
            if (nt < 2) { h0lA += pA; h0rA += qA; h0lB += pB; h0rB += qB; }
            else        { h1lA += pA; h1rA += qA; h1lB += pB; h1rB += qB; }
        }
        h0lA = qreduce(h0lA); h1lA = qreduce(h1lA);
        h0rA = qreduce(h0rA); h1rA = qreduce(h1rA);
        h0lB = qreduce(h0lB); h1lB = qreduce(h1lB);
        h0rB = qreduce(h0rB); h1rB = qreduce(h1rB);
        if (t == 0) {
            if (rA < N_NODES) {
                g_el[rA * 8 + 2 * wn] = h0lA;  g_el[rA * 8 + 2 * wn + 1] = h1lA;
                g_er[rA * 8 + 2 * wn] = h0rA;  g_er[rA * 8 + 2 * wn + 1] = h1rA;
            }
            if (rB < N_NODES) {
                g_el[rB * 8 + 2 * wn] = h0lB;  g_el[rB * 8 + 2 * wn + 1] = h1lB;
                g_er[rB * 8 + 2 * wn] = h0rB;  g_er[rB * 8 + 2 * wn + 1] = h1rB;
            }
        }
        #pragma unroll
        for (int nt = 0; nt < 4; nt++) {
            int c = n0 + nt * 8 + 2 * t;
            if (rA < N_NODES)
                *(__half2*)&feat16[(size_t)rA * 128 + c] =
                    __floats2half2_rn(acc[mt][nt][0], acc[mt][nt][1]);
            if (rB < N_NODES)
                *(__half2*)&feat16[(size_t)rB * 128 + c] =
                    __floats2half2_rn(acc[mt][nt][2], acc[mt][nt][3]);
        }
    }
}

__device__ __forceinline__ float leaky(float x) { return x > 0.f ? x : NEG * x; }

// ---------------- fused edge softmax + aggregate + ELU (warp per node) -------
// Softmax is shift-invariant: skip the max pass (exp args bounded ~|8|).
__global__ void edge128_kernel(const __half* __restrict__ feat16,
                               __half* __restrict__ hout) {
    int node = (blockIdx.x * blockDim.x + threadIdx.x) >> 5;
    int lane = threadIdx.x & 31;
    if (node >= N_NODES) return;
    int beg = g_off[node], end = g_off[node + 1];
    int head = lane >> 2;
    float erh = g_er[node * 8 + head];

    float4 acc = make_float4(0.f, 0.f, 0.f, 0.f);
    float den = 0.f;
    int j = beg;
    for (; j + 4 <= end; j += 4) {
        int s0 = g_ssrc[j], s1 = g_ssrc[j + 1], s2 = g_ssrc[j + 2], s3 = g_ssrc[j + 3];
        float w0 = __expf(leaky(g_el[s0 * 8 + head] + erh));
        float w1 = __expf(leaky(g_el[s1 * 8 + head] + erh));
        float w2 = __expf(leaky(g_el[s2 * 8 + head] + erh));
        float w3 = __expf(leaky(g_el[s3 * 8 + head] + erh));
        uint2 r0 = *(const uint2*)(feat16 + (size_t)s0 * 128 + lane * 4);
        uint2 r1 = *(const uint2*)(feat16 + (size_t)s1 * 128 + lane * 4);
        uint2 r2 = *(const uint2*)(feat16 + (size_t)s2 * 128 + lane * 4);
        uint2 r3 = *(const uint2*)(feat16 + (size_t)s3 * 128 + lane * 4);
        {
            float2 a01 = __half22float2(*(__half2*)&r0.x);
            float2 a23 = __half22float2(*(__half2*)&r0.y);
            acc.x += a01.x * w0; acc.y += a01.y * w0;
            acc.z += a23.x * w0; acc.w += a23.y * w0;
        }
        {
            float2 a01 = __half22float2(*(__half2*)&r1.x);
            float2 a23 = __half22float2(*(__half2*)&r1.y);
            acc.x += a01.x * w1; acc.y += a01.y * w1;
            acc.z += a23.x * w1; acc.w += a23.y * w1;
        }
        {
            float2 a01 = __half22float2(*(__half2*)&r2.x);
            float2 a23 = __half22float2(*(__half2*)&r2.y);
            acc.x += a01.x * w2; acc.y += a01.y * w2;
            acc.z += a23.x * w2; acc.w += a23.y * w2;
        }
        {
            float2 a01 = __half22float2(*(__half2*)&r3.x);
            float2 a23 = __half22float2(*(__half2*)&r3.y);
            acc.x += a01.x * w3; acc.y += a01.y * w3;
            acc.z += a23.x * w3; acc.w += a23.y * w3;
        }
        den += w0 + w1 + w2 + w3;
    }
    for (; j < end; j++) {
        int s = g_ssrc[j];
        float w = __expf(leaky(g_el[s * 8 + head] + erh));
        uint2 r = *(const uint2*)(feat16 + (size_t)s * 128 + lane * 4);
        float2 a01 = __half22float2(*(__half2*)&r.x);
        float2 a23 = __half22float2(*(__half2*)&r.y);
        acc.x += a01.x * w; acc.y += a01.y * w;
        acc.z += a23.x * w; acc.w += a23.y * w;
        den += w;
    }

    float4 o = make_float4(0.f, 0.f, 0.f, 0.f);
    if (den > 0.f) {
        float inv = 1.f / den;
        o.x = acc.x * inv; o.y = acc.y * inv; o.z = acc.z * inv; o.w = acc.w * inv;
        o.x = o.x > 0.f ? o.x : expm1f(o.x);
        o.y = o.y > 0.f ? o.y : expm1f(o.y);
        o.z = o.z > 0.f ? o.z : expm1f(o.z);
        o.w = o.w > 0.f ? o.w : expm1f(o.w);
    }
    uint2 st;
    *(__half2*)&st.x = __floats2half2_rn(o.x, o.y);
    *(__half2*)&st.y = __floats2half2_rn(o.z, o.w);
    *(uint2*)(hout + (size_t)node * 128 + lane * 4) = st;
}

// ---------------- final layer: GEMM (N,128)@(128,10) + el/er -----------------
__global__ void gemm10_kernel(const __half* __restrict__ hin,
                              const float* __restrict__ W,
                              const float* __restrict__ al,
                              const float* __restrict__ ar) {
    __shared__ float Ws[128 * NCLS];
    int tid = threadIdx.x;
    for (int i = tid; i < 128 * NCLS; i += blockDim.x) Ws[i] = W[i];
    __syncthreads();
    int node = (blockIdx.x * blockDim.x + tid) >> 5;
    int lane = tid & 31;
    if (node >= N_NODES) return;
    float acc[NCLS];
    #pragma unroll
    for (int c = 0; c < NCLS; c++) acc[c] = 0.f;
    #pragma unroll
    for (int c4 = 0; c4 < 4; c4++) {
        int k = c4 * 32 + lane;
        float hv = __half2float(hin[(size_t)node * 128 + k]);
        #pragma unroll
        for (int c = 0; c < NCLS; c++) acc[c] += hv * Ws[k * NCLS + c];
    }
    #pragma unroll
    for (int c = 0; c < NCLS; c++) {
        #pragma unroll
        for (int d = 16; d >= 1; d >>= 1)
            acc[c] += __shfl_xor_sync(0xffffffffu, acc[c], d);
    }
    if (lane == 0) {
        float e_l = 0.f, e_r = 0.f;
        #pragma unroll
        for (int c = 0; c < NCLS; c++) {
            g_feat5[node * NCLS + c] = acc[c];
            e_l += acc[c] * al[c];
            e_r += acc[c] * ar[c];
        }
        g_el5[node] = e_l;
        g_er5[node] = e_r;
    }
}

__global__ void edge10_kernel(float* __restrict__ out) {
    int node = (blockIdx.x * blockDim.x + threadIdx.x) >> 5;
    int lane = threadIdx.x & 31;
    if (node >= N_NODES) return;
    int beg = g_off[node], end = g_off[node + 1];
    float ern = g_er5[node];
    float acc = 0.f, den = 0.f;
    for (int j = beg; j < end; j++) {
        int s = g_ssrc[j];
        float ex = __expf(leaky(g_el5[s] + ern));
        den += ex;
        if (lane < NCLS) acc += g_feat5[s * NCLS + lane] * ex;
    }
    if (lane < NCLS) out[node * NCLS + lane] = den > 0.f ? acc / den : 0.f;
}

// ---------------- launch -----------------------------------------------------
extern "C" void kernel_launch(void* const* d_in, const int* in_sizes, int n_in,
                              void* d_out, int out_size) {
    const float* h   = (const float*)d_in[0];
    const int*   src = (const int*)d_in[1];
    const int*   dst = (const int*)d_in[2];
    const float* W[5]; const float* al[5]; const float* ar[5];
    for (int i = 0; i < 5; i++) {
        W[i]  = (const float*)d_in[3 + 3 * i];
        al[i] = (const float*)d_in[4 + 3 * i];
        ar[i] = (const float*)d_in[5 + 3 * i];
    }

    __half *feat16, *hA, *hB;
    cudaGetSymbolAddress((void**)&feat16, g_feat16);
    cudaGetSymbolAddress((void**)&hA, g_hA);
    cudaGetSymbolAddress((void**)&hB, g_hB);

    const int smem_g = (64 + 128 + 128) * PADH * (int)sizeof(__half);   // 87040
    static bool s_init = false;
    static cudaStream_t s_csr;
    static cudaEvent_t ev_fork, ev_join;
    if (!s_init) {
        cudaFuncSetAttribute(gemm_fp16<float>,
                             cudaFuncAttributeMaxDynamicSharedMemorySize, smem_g);
        cudaFuncSetAttribute(gemm_fp16<__half>,
                             cudaFuncAttributeMaxDynamicSharedMemorySize, smem_g);
        cudaStreamCreateWithFlags(&s_csr, cudaStreamNonBlocking);
        cudaEventCreateWithFlags(&ev_fork, cudaEventDisableTiming);
        cudaEventCreateWithFlags(&ev_join, cudaEventDisableTiming);
        s_init = true;
    }

    // ---- fork: CSR build on side stream, overlapped with W-split + layer-0 ----
    cudaEventRecord(ev_fork, 0);
    cudaStreamWaitEvent(s_csr, ev_fork, 0);
    zero_kernel<<<(N_NODES + 255) / 256, 256, 0, s_csr>>>();
    count_kernel<<<(N_EDGES + 255) / 256, 256, 0, s_csr>>>(dst);
    scan1_kernel<<<NPART, SCAN_BLK, 0, s_csr>>>();
    scan3_kernel<<<(N_NODES + 255) / 256, 256, 0, s_csr>>>();
    scatter_kernel<<<(N_EDGES + 255) / 256, 256, 0, s_csr>>>(src, dst);
    cudaEventRecord(ev_join, s_csr);

    const int node_warp_grid = (N_NODES * 32 + 255) / 256;  // warp per node
    const int gemm_grid = (N_NODES + 63) / 64;

    // W pre-split (all 4 layers, one launch)
    {
        dim3 g(64, 4);
        wsplit_kernel<<<g, 256>>>(W[0], W[1], W[2], W[3]);
    }

    // layer 0 feature path (independent of CSR)
    gemm_fp16<float><<<gemm_grid, 256, smem_g>>>(h, 0, feat16, al[0], ar[0]);
    cudaStreamWaitEvent(0, ev_join, 0);   // join before first edge kernel
    edge128_kernel<<<node_warp_grid, 256>>>(feat16, hA);

    const __half* cur = hA;
    __half* bufs[2] = { hA, hB };
    for (int L = 1; L < 4; L++) {
        gemm_fp16<__half><<<gemm_grid, 256, smem_g>>>(cur, L, feat16, al[L], ar[L]);
        edge128_kernel<<<node_warp_grid, 256>>>(feat16, bufs[L & 1]);
        cur = bufs[L & 1];
    }
    gemm10_kernel<<<node_warp_grid, 256>>>(cur, W[4], al[4], ar[4]);
    edge10_kernel<<<node_warp_grid, 256>>>((float*)d_out);
}